// round 10
// baseline (speedup 1.0000x reference)
#include <cuda_runtime.h>

#define BATCH 4
#define NV 4096
#define NM 8192
#define BIGF 1e10f

#define NSTRIP 8               // m-strips per batch
#define STRIPM (NM / NSTRIP)   // 1024
#define BM     128             // p-cols per tile
#define NTILE  (STRIPM / BM)   // 8
#define NVB    (NV / 128)      // 32 v-row blocks

typedef unsigned long long u64;

// ------------------------ scratch (device globals, no allocs) ---------------
// g_dmin: [0, BATCH*NV) = d1 (per v row), [BATCH*NV, +BATCH*NM) = d2 (per p col)
// encoded floats; initialized to 0xFFFFFFFF by a memset node each launch.
__device__ unsigned g_dmin[BATCH * (NV + NM)];
__device__ float g_sum1[BATCH], g_sum2[BATCH], g_cnt[BATCH];
__device__ unsigned g_done;

// order-preserving float<->uint encoding so unsigned atomicMin == float min
__device__ __forceinline__ unsigned encf(float f) {
    unsigned u = __float_as_uint(f);
    return (u & 0x80000000u) ? ~u : (u | 0x80000000u);
}
__device__ __forceinline__ float decf(unsigned u) {
    return (u & 0x80000000u) ? __uint_as_float(u & 0x7FFFFFFFu)
                             : __uint_as_float(~u);
}

// ------------------------ packed f32x2 helpers ------------------------------
__device__ __forceinline__ u64 pack2(float lo, float hi) {
    u64 d;
    asm("mov.b64 %0, {%1, %2};" : "=l"(d) : "f"(lo), "f"(hi));
    return d;
}
__device__ __forceinline__ u64 fma2(u64 a, u64 b, u64 c) {
    u64 d;
    asm("fma.rn.f32x2 %0, %1, %2, %3;" : "=l"(d) : "l"(a), "l"(b), "l"(c));
    return d;
}
__device__ __forceinline__ u64 add2(u64 a, u64 b) {
    u64 d;
    asm("add.rn.f32x2 %0, %1, %2;" : "=l"(d) : "l"(a), "l"(b));
    return d;
}
__device__ __forceinline__ float2 asf2(u64 v) {
    union { u64 u; float2 f; } c; c.u = v; return c.f;
}

// ------------------------ 1) fused transform + pairwise min ------------------
// Block: 128 v-rows x 1024 p-cols (8 tiles of 128), 256 threads, grid=1024.
__global__ __launch_bounds__(256, 3) void chamfer_kernel(
        const float* __restrict__ vert, const float* __restrict__ pc) {
    __shared__ u64   spx[2][BM];
    __shared__ u64   spy[2][BM];
    __shared__ u64   spz[2][BM];
    __shared__ u64   spw[2][BM];
    __shared__ float sred[128 * 17];   // padded reduction scratch
    __shared__ __align__(16) float svx[128], svy[128], svz[128], scv[128];

    int b   = blockIdx.z;
    int y   = blockIdx.y;
    int n0  = y * 128;
    int s   = blockIdx.x;
    int mb0 = s * STRIPM;
    int tid = threadIdx.x;
    int ty  = tid >> 4;
    int tx  = tid & 15;

    // one block zeroes the final-stage accumulators (nobody reads them in K1)
    if (blockIdx.x == 0 && blockIdx.y == 0 && blockIdx.z == 0 && tid < BATCH) {
        g_sum1[tid] = 0.f; g_sum2[tid] = 0.f; g_cnt[tid] = 0.f;
        if (tid == 0) g_done = 0u;
    }

    // ---- transform my v rows (top surface gather) + p tile 0 ----
    if (tid < 128) {
        int r = n0 + tid;
        int i = r >> 6, k = r & 63;
        // vertices[b, c, i, 31, k]; shape (4,3,64,32,64)
        int base = ((b * 3) * 64 + i) * 2048 + 31 * 64 + k;
        float v0 = (vert[base]          - 0.5f) * 2.f;
        float v1 = (vert[base + 131072] - 0.5f) * 2.f;
        float v2 = (vert[base + 262144] - 0.5f) * 2.f;
        svx[tid] = v0; svy[tid] = v1; svz[tid] = v2;
        scv[tid] = fmaf(v0, v0, fmaf(v1, v1, v2 * v2));
    } else {
        int u = tid - 128;
        int m = mb0 + u;
        float p0 = pc[(b * 3 + 0) * NM + m];
        float p1 = pc[(b * 3 + 1) * NM + m];
        float p2 = pc[(b * 3 + 2) * NM + m];
        bool valid = (p0 != 0.f) || (p1 != 0.f) || (p2 != 0.f);
        float cp = valid ? fmaf(p0, p0, fmaf(p1, p1, p2 * p2)) : BIGF;
        spx[0][u] = pack2(-2.f * p0, -2.f * p0);
        spy[0][u] = pack2(-2.f * p1, -2.f * p1);
        spz[0][u] = pack2(-2.f * p2, -2.f * p2);
        spw[0][u] = pack2(cp, cp);
    }
    __syncthreads();

    // ---- my 8 v-rows as packed pairs (LDS.64 from SoA smem) ----
    u64 vx2[4], vy2[4], vz2[4], cv2[4];
#pragma unroll
    for (int q = 0; q < 4; q++) {
        int r = 8 * ty + 2 * q;
        vx2[q] = *(const u64*)&svx[r];
        vy2[q] = *(const u64*)&svy[r];
        vz2[q] = *(const u64*)&svz[r];
        cv2[q] = *(const u64*)&scv[r];
    }

    float rmin[8];
#pragma unroll
    for (int k = 0; k < 8; k++) rmin[k] = 3.4e38f;

    for (int t = 0; t < NTILE; t++) {
        int cur = t & 1, nxt = cur ^ 1;

        // prefetch + transform next tile (threads 128..255)
        float pnx, pny, pnz, pnw;
        int u = tid - 128;
        if (tid >= 128 && t + 1 < NTILE) {
            int m = mb0 + (t + 1) * BM + u;
            float p0 = pc[(b * 3 + 0) * NM + m];
            float p1 = pc[(b * 3 + 1) * NM + m];
            float p2 = pc[(b * 3 + 2) * NM + m];
            bool valid = (p0 != 0.f) || (p1 != 0.f) || (p2 != 0.f);
            pnw = valid ? fmaf(p0, p0, fmaf(p1, p1, p2 * p2)) : BIGF;
            pnx = -2.f * p0; pny = -2.f * p1; pnz = -2.f * p2;
        }

        float cmin[8];
#pragma unroll
        for (int j = 0; j < 8; j++) cmin[j] = 3.4e38f;

#pragma unroll
        for (int j = 0; j < 8; j++) {
            int c = tx + 16 * j;
            u64 pxx = spx[cur][c];
            u64 pyy = spy[cur][c];
            u64 pzz = spz[cur][c];
            u64 cpp = spw[cur][c];
#pragma unroll
            for (int q = 0; q < 4; q++) {
                // tq = cp - 2 v.p  (both rows of the pair)
                u64 tq = fma2(vz2[q], pzz, cpp);
                tq = fma2(vy2[q], pyy, tq);
                tq = fma2(vx2[q], pxx, tq);
                float2 a = asf2(tq);
                rmin[2 * q]     = fminf(rmin[2 * q],     a.x);   // cv added at end
                rmin[2 * q + 1] = fminf(rmin[2 * q + 1], a.y);
                float2 e = asf2(add2(tq, cv2[q]));               // full d for p-side
                cmin[j] = fminf(cmin[j], fminf(e.x, e.y));
            }
        }

        // commit prefetched tile (everyone is past tile t-1's reads)
        if (tid >= 128 && t + 1 < NTILE) {
            spx[nxt][u] = pack2(pnx, pnx);
            spy[nxt][u] = pack2(pny, pny);
            spz[nxt][u] = pack2(pnz, pnz);
            spw[nxt][u] = pack2(pnw, pnw);
        }

        // ---- dist2 partials: col tx+16j, across ty ----
#pragma unroll
        for (int j = 0; j < 8; j++)
            sred[(tx + 16 * j) * 17 + ty] = cmin[j];
        __syncthreads();

        if (tid < 128) {
            float mn = sred[tid * 17];
#pragma unroll
            for (int k = 1; k < 16; k++) mn = fminf(mn, sred[tid * 17 + k]);
            atomicMin(&g_dmin[BATCH * NV + b * NM + mb0 + t * BM + tid], encf(mn));
        }
        __syncthreads();
    }

    // ---- dist1 partial: once per block ----
#pragma unroll
    for (int k = 0; k < 8; k++)
        sred[(8 * ty + k) * 17 + tx] = rmin[k];
    __syncthreads();
    if (tid < 128) {
        float mn = sred[tid * 17];
#pragma unroll
        for (int k = 1; k < 16; k++) mn = fminf(mn, sred[tid * 17 + k]);
        atomicMin(&g_dmin[b * NV + n0 + tid], encf(mn + scv[tid]));
    }
}

// ------------------------ 2) final reduction --------------------------------
// 64 blocks (16 per batch). Only 192 KB of mins + 384 KB mask to read.
__global__ void final_kernel(const float* __restrict__ pc,
                             float* __restrict__ out) {
    __shared__ float sh[24];
    __shared__ bool last;
    int tid  = threadIdx.x;
    int b    = blockIdx.x >> 4;
    int part = blockIdx.x & 15;
    int lane = tid & 31, wid = tid >> 5;

    // dist1: 256 v rows per block, 1 per thread
    float s1 = decf(g_dmin[b * NV + part * 256 + tid]);

    // dist2: 512 p cols per block, 2 per thread (uint2 + float2 mask reads)
    float s2 = 0.f, c2 = 0.f;
    {
        int m = part * 512 + tid * 2;
        uint2  d  = *(const uint2*) &g_dmin[BATCH * NV + b * NM + m];
        float2 px = *(const float2*)&pc[(b * 3 + 0) * NM + m];
        float2 py = *(const float2*)&pc[(b * 3 + 1) * NM + m];
        float2 pz = *(const float2*)&pc[(b * 3 + 2) * NM + m];
        if (px.x != 0.f || py.x != 0.f || pz.x != 0.f) { s2 += decf(d.x); c2 += 1.f; }
        if (px.y != 0.f || py.y != 0.f || pz.y != 0.f) { s2 += decf(d.y); c2 += 1.f; }
    }

    // warp sums -> cross-warp via smem -> warp 0 total
#pragma unroll
    for (int o = 16; o > 0; o >>= 1) {
        s1 += __shfl_down_sync(0xffffffffu, s1, o);
        s2 += __shfl_down_sync(0xffffffffu, s2, o);
        c2 += __shfl_down_sync(0xffffffffu, c2, o);
    }
    if (lane == 0) { sh[wid] = s1; sh[8 + wid] = s2; sh[16 + wid] = c2; }
    __syncthreads();

    if (tid == 0) {
        float t1 = 0.f, t2 = 0.f, tc = 0.f;
#pragma unroll
        for (int w = 0; w < 8; w++) { t1 += sh[w]; t2 += sh[8 + w]; tc += sh[16 + w]; }
        atomicAdd(&g_sum1[b], t1);
        atomicAdd(&g_sum2[b], t2);
        atomicAdd(&g_cnt[b],  tc);
        __threadfence();
        unsigned done = atomicAdd(&g_done, 1u);
        last = (done == gridDim.x - 1);
    }
    __syncthreads();

    if (last && tid == 0) {
        float acc = 0.f;
        for (int bb = 0; bb < BATCH; bb++)
            acc += g_sum1[bb] / (float)NV + g_sum2[bb] / fmaxf(g_cnt[bb], 1.f);
        out[0] = acc / (float)BATCH;
    }
}

// ------------------------ launch --------------------------------------------
extern "C" void kernel_launch(void* const* d_in, const int* in_sizes, int n_in,
                              void* d_out, int out_size) {
    const float* vert = (const float*)d_in[0];
    const float* pc   = (const float*)d_in[1];
    if (in_sizes[0] == BATCH * 3 * NM) {   // defensive input identification
        vert = (const float*)d_in[1];
        pc   = (const float*)d_in[0];
    }

    // init min arrays to 0xFFFFFFFF (> any encoded float) — capturable memset
    void* dmin_ptr = nullptr;
    cudaGetSymbolAddress(&dmin_ptr, g_dmin);
    cudaMemsetAsync(dmin_ptr, 0xFF, BATCH * (NV + NM) * sizeof(unsigned), 0);

    dim3 grid(NSTRIP, NVB, BATCH);
    chamfer_kernel<<<grid, 256>>>(vert, pc);
    final_kernel<<<64, 256>>>(pc, (float*)d_out);
}